// round 1
// baseline (speedup 1.0000x reference)
#include <cuda_runtime.h>

// ConvCapsuleLayer: B=2, H=W=48, IN_CAPS=8, ATOMS=16, KER=3, OUT_CAPS=16, ROUTINGS=3
// Ho=Wo=46, N = 2*46*46 = 4232 positions. One CTA per position, 256 threads.
//
// Algebraic restructure (no votes materialization):
//   votes[ki,o] = pose[ki] @ W[i,o]            (4x4 matrices)
//   s[o]        = sum_i ( sum_k coup[k,i,o]*pose[k,i] ) @ W[i,o]
//   logit_upd[ki,o] = sum_{a,b} pose[ki][a,b] * Q[i,o][a,b],
//       Q[i,o][a,b] = sum_c W[i,o][b,c] * v[o][a,c]

#define HH 48
#define WW 48
#define CIN 136          // IN_CAPS*(ATOMS+1)
#define HO 46
#define WO 46
#define KKI 72           // 9 * 8
#define NOUT 16
#define NTHREADS 256
#define ROUTINGS 3

__global__ __launch_bounds__(NTHREADS, 1)
void capsule_kernel(const float* __restrict__ x,
                    const float* __restrict__ Wg,
                    float* __restrict__ out)
{
    __shared__ __align__(16) float W_s[8 * 16 * 16];     // [i][o][b*4+c]
    __shared__ __align__(16) float pose_s[KKI * 16];     // [ki][a*4+b]
    __shared__ __align__(16) float act_s[KKI];
    __shared__ __align__(16) float logits[KKI * NOUT];   // [ki][o]
    __shared__ __align__(16) float coup[KKI * NOUT];     // [ki][o]
    __shared__ __align__(16) float PQ[2048];             // P: [o][i][16] / Q: [i][o][16]
    __shared__ __align__(16) float s_s[NOUT * 16];       // [o][a*4+c]
    __shared__ __align__(16) float v_s[NOUT * 16];       // [o][a*4+c]

    const int tid = threadIdx.x;
    const int n   = blockIdx.x;
    const int b   = n / (HO * WO);
    const int rem = n % (HO * WO);
    const int ho  = rem / WO;
    const int wo  = rem % WO;

    // ---- load W (2048 floats) ----
    #pragma unroll
    for (int idx = tid; idx < 2048; idx += NTHREADS)
        W_s[idx] = Wg[idx];

    // ---- load pose + act: 72 capsules x 17 values ----
    for (int idx = tid; idx < KKI * 17; idx += NTHREADS) {
        int ki = idx / 17;
        int a  = idx - ki * 17;
        int k  = ki >> 3;
        int i  = ki & 7;
        int di = k / 3;
        int dj = k - di * 3;
        float val = x[(size_t)(((b * HH + ho + di) * WW) + (wo + dj)) * CIN + i * 17 + a];
        if (a < 16) pose_s[ki * 16 + a] = val;
        else        act_s[ki] = val;
    }
    for (int idx = tid; idx < KKI * NOUT; idx += NTHREADS)
        logits[idx] = 0.0f;
    __syncthreads();

    float vout = 0.0f;  // this thread's final v value (o = tid>>4, e = tid&15)

    #pragma unroll 1
    for (int r = 0; r < ROUTINGS; r++) {
        // ---- A: coup[ki][o] = softmax_o(logits[ki]) * act[ki] ----
        if (tid < KKI) {
            const float* lrow = &logits[tid * 16];
            float m = lrow[0];
            #pragma unroll
            for (int o = 1; o < 16; o++) m = fmaxf(m, lrow[o]);
            float e[16];
            float sum = 0.0f;
            #pragma unroll
            for (int o = 0; o < 16; o++) { e[o] = __expf(lrow[o] - m); sum += e[o]; }
            float scale = act_s[tid] / sum;
            #pragma unroll
            for (int o = 0; o < 16; o++) coup[tid * 16 + o] = e[o] * scale;
        }
        __syncthreads();

        // ---- B: P[o][i][e] = sum_k coup[(k*8+i)][o] * pose[(k*8+i)][e] ----
        {
            int pair = tid >> 1;          // 0..127
            int o    = pair >> 3;
            int i    = pair & 7;
            int half = tid & 1;           // e in [half*8, half*8+8)
            float4 a0 = make_float4(0.f, 0.f, 0.f, 0.f);
            float4 a1 = make_float4(0.f, 0.f, 0.f, 0.f);
            #pragma unroll
            for (int k = 0; k < 9; k++) {
                int ki  = k * 8 + i;
                float c = coup[ki * 16 + o];
                const float4* pr = (const float4*)&pose_s[ki * 16 + half * 8];
                float4 p0 = pr[0], p1 = pr[1];
                a0.x += c * p0.x; a0.y += c * p0.y; a0.z += c * p0.z; a0.w += c * p0.w;
                a1.x += c * p1.x; a1.y += c * p1.y; a1.z += c * p1.z; a1.w += c * p1.w;
            }
            float4* dst = (float4*)&PQ[(o * 8 + i) * 16 + half * 8];
            dst[0] = a0; dst[1] = a1;
        }
        __syncthreads();

        // ---- C: s[o][a*4+c] = sum_i sum_b P[o][i][a*4+b] * W[i][o][b*4+c] ----
        if (tid < 64) {
            int o = tid >> 2, a = tid & 3;
            float4 acc = make_float4(0.f, 0.f, 0.f, 0.f);
            #pragma unroll
            for (int i = 0; i < 8; i++) {
                float4 p = *(const float4*)&PQ[(o * 8 + i) * 16 + a * 4];
                const float4* wr = (const float4*)&W_s[(i * 16 + o) * 16];
                float4 w0 = wr[0], w1 = wr[1], w2 = wr[2], w3 = wr[3];
                acc.x += p.x * w0.x + p.y * w1.x + p.z * w2.x + p.w * w3.x;
                acc.y += p.x * w0.y + p.y * w1.y + p.z * w2.y + p.w * w3.y;
                acc.z += p.x * w0.z + p.y * w1.z + p.z * w2.z + p.w * w3.z;
                acc.w += p.x * w0.w + p.y * w1.w + p.z * w2.w + p.w * w3.w;
            }
            *(float4*)&s_s[o * 16 + a * 4] = acc;
        }
        __syncthreads();

        // ---- D: squash. Each thread owns (o = tid>>4, e = tid&15) ----
        {
            int o = tid >> 4, e = tid & 15;
            const float4* sr = (const float4*)&s_s[o * 16];
            float4 s0 = sr[0], s1 = sr[1], s2 = sr[2], s3 = sr[3];
            float sq = s0.x*s0.x + s0.y*s0.y + s0.z*s0.z + s0.w*s0.w
                     + s1.x*s1.x + s1.y*s1.y + s1.z*s1.z + s1.w*s1.w
                     + s2.x*s2.x + s2.y*s2.y + s2.z*s2.z + s2.w*s2.w
                     + s3.x*s3.x + s3.y*s3.y + s3.z*s3.z + s3.w*s3.w;
            float se    = s_s[o * 16 + e];
            float scale = (sq / (1.0f + sq)) * rsqrtf(sq + 1e-7f);
            vout = se * scale;
            v_s[tid] = vout;
        }
        if (r == ROUTINGS - 1) break;
        __syncthreads();

        // ---- E: Q[i][o][a*4+b] = sum_c v[o][a*4+c] * W[i][o][b*4+c] ----
        {
            int io   = tid >> 1;          // 0..127
            int i    = io >> 4;
            int o    = io & 15;
            int half = tid & 1;           // a in {half*2, half*2+1}
            const float4* wr = (const float4*)&W_s[(i * 16 + o) * 16];
            float4 w0 = wr[0], w1 = wr[1], w2 = wr[2], w3 = wr[3];
            #pragma unroll
            for (int aa = 0; aa < 2; aa++) {
                int a = half * 2 + aa;
                float4 va = *(const float4*)&v_s[o * 16 + a * 4];
                float4 q;
                q.x = va.x*w0.x + va.y*w0.y + va.z*w0.z + va.w*w0.w;
                q.y = va.x*w1.x + va.y*w1.y + va.z*w1.z + va.w*w1.w;
                q.z = va.x*w2.x + va.y*w2.y + va.z*w2.z + va.w*w2.w;
                q.w = va.x*w3.x + va.y*w3.y + va.z*w3.z + va.w*w3.w;
                *(float4*)&PQ[(i * 16 + o) * 16 + a * 4] = q;
            }
        }
        __syncthreads();

        // ---- F: logits[ki][o] += dot16(pose[ki], Q[i][o]) ----
        for (int idx = tid; idx < KKI * NOUT; idx += NTHREADS) {
            int ki = idx >> 4;
            int o  = idx & 15;
            int i  = ki & 7;
            const float4* pr = (const float4*)&pose_s[ki * 16];
            const float4* qr = (const float4*)&PQ[(i * 16 + o) * 16];
            float d = 0.0f;
            #pragma unroll
            for (int j = 0; j < 4; j++) {
                float4 p = pr[j], q = qr[j];
                d += p.x*q.x + p.y*q.y + p.z*q.z + p.w*q.w;
            }
            logits[idx] += d;
        }
        __syncthreads();
    }

    // ---- write output: out[n][o][e], o = tid>>4, e = tid&15 ----
    out[(size_t)n * 256 + tid] = vout;
}

extern "C" void kernel_launch(void* const* d_in, const int* in_sizes, int n_in,
                              void* d_out, int out_size)
{
    const float* x = (const float*)d_in[0];
    const float* W = (const float*)d_in[1];
    // Defensive: W has exactly 2048 elements; input has 626688.
    if (n_in >= 2 && in_sizes[0] == 2048) {
        const float* t = x; x = W; W = t;
    }
    float* out = (float*)d_out;
    const int nblocks = 2 * HO * WO;  // 4232
    capsule_kernel<<<nblocks, NTHREADS>>>(x, W, out);
}